// round 6
// baseline (speedup 1.0000x reference)
#include <cuda_runtime.h>
#include <cuda_bf16.h>
#include <stdint.h>
#include <math.h>

#define D      256
#define MAXB   8192
#define NCROPS 10
#define SROW   20   // smem row stride in 32-bit words (32 bf16 + 8 pad = 40 halves)

// Scratch (device globals; no allocation allowed)
__device__ float              g_xf[MAXB * D];           // normalized x, fp32 (8 MB)
__device__ __nv_bfloat16      g_xh[MAXB * D];           // normalized x, bf16 (4 MB)
__device__ unsigned long long g_best[MAXB];             // (ordered_float<<32)|col

// ---------------------------------------------------------------------------
// Kernel 1: row L2-normalize, emit fp32 + bf16 copies, reset per-row argmax,
// zero the output accumulator.
// ---------------------------------------------------------------------------
__global__ void koleo_normalize(const float* __restrict__ s, float* __restrict__ out) {
    int row = blockIdx.x;
    int t   = threadIdx.x;          // blockDim = 256 = D
    float v = s[row * D + t];
    float ss = v * v;
    #pragma unroll
    for (int o = 16; o; o >>= 1) ss += __shfl_xor_sync(0xffffffffu, ss, o);
    __shared__ float ws[8];
    if ((t & 31) == 0) ws[t >> 5] = ss;
    __syncthreads();
    if (t == 0) {
        float a = 0.f;
        #pragma unroll
        for (int i = 0; i < 8; i++) a += ws[i];
        ws[0] = a;
        g_best[row] = 0ull;         // any real key has high word >= ~0x3FC00000
        if (row == 0) out[0] = 0.f;
    }
    __syncthreads();
    float norm = sqrtf(ws[0]);
    float xn = v / fmaxf(norm, 1e-8f);
    g_xf[row * D + t] = xn;
    g_xh[row * D + t] = __float2bfloat16(xn);
}

// ---------------------------------------------------------------------------
// Kernel 2: fused x @ x^T with per-row running argmax (diagonal excluded).
// 128x128 CTA tile, BK=32, double-buffered smem, mma.sync.m16n8k16 bf16->f32.
// Warp layout: 4x2 warps, each computes 32x64 (2 m-frags x 8 n-frags).
// ---------------------------------------------------------------------------
__global__ void __launch_bounds__(256) koleo_gemm_argmax(int B) {
    __shared__ uint32_t sA[2][128 * SROW];
    __shared__ uint32_t sB[2][128 * SROW];

    const int t    = threadIdx.x;
    const int lane = t & 31, warp = t >> 5;
    const int wm = warp & 3, wn = warp >> 2;   // 4x2 warp grid
    const int m0 = wm * 32,  n0 = wn * 64;
    const int qr = lane >> 2, qc = lane & 3;
    const int rowA = blockIdx.y * 128;
    const int rowB = blockIdx.x * 128;
    const uint2* gp = (const uint2*)g_xh;      // 4 halves per uint2; row = 64 uint2

    float acc[2][8][4];
    #pragma unroll
    for (int mf = 0; mf < 2; mf++)
        #pragma unroll
        for (int nf = 0; nf < 8; nf++)
            #pragma unroll
            for (int e = 0; e < 4; e++) acc[mf][nf][e] = 0.f;

    uint2 ra[4], rb[4];
    // prefetch k-chunk 0
    #pragma unroll
    for (int i = 0; i < 4; i++) {
        int u = t + i * 256;
        int r = u >> 3, c2 = u & 7;
        ra[i] = gp[(rowA + r) * 64 + c2];
        rb[i] = gp[(rowB + r) * 64 + c2];
    }
    #pragma unroll
    for (int i = 0; i < 4; i++) {
        int u = t + i * 256;
        int r = u >> 3, c2 = u & 7;
        ((uint2*)sA[0])[r * 10 + c2] = ra[i];
        ((uint2*)sB[0])[r * 10 + c2] = rb[i];
    }
    __syncthreads();

    int buf = 0;
    for (int kc = 0; kc < 8; kc++) {           // K = 256 = 8 * 32
        if (kc < 7) {
            #pragma unroll
            for (int i = 0; i < 4; i++) {
                int u = t + i * 256;
                int r = u >> 3, c2 = u & 7;
                ra[i] = gp[(rowA + r) * 64 + (kc + 1) * 8 + c2];
                rb[i] = gp[(rowB + r) * 64 + (kc + 1) * 8 + c2];
            }
        }
        const uint32_t* As = sA[buf];
        const uint32_t* Bs = sB[buf];
        #pragma unroll
        for (int kk2 = 0; kk2 < 2; kk2++) {    // two k16 steps per chunk
            const int kw = kk2 * 8 + qc;
            uint32_t af[2][4];
            #pragma unroll
            for (int mf = 0; mf < 2; mf++) {
                int base = (m0 + mf * 16 + qr) * SROW + kw;
                af[mf][0] = As[base];
                af[mf][1] = As[base + 8 * SROW];
                af[mf][2] = As[base + 4];
                af[mf][3] = As[base + 8 * SROW + 4];
            }
            uint32_t bfr[8][2];
            #pragma unroll
            for (int nf = 0; nf < 8; nf++) {
                int nb = (n0 + nf * 8 + qr) * SROW + kw;
                bfr[nf][0] = Bs[nb];
                bfr[nf][1] = Bs[nb + 4];
            }
            #pragma unroll
            for (int mf = 0; mf < 2; mf++)
                #pragma unroll
                for (int nf = 0; nf < 8; nf++) {
                    asm volatile(
                        "mma.sync.aligned.m16n8k16.row.col.f32.bf16.bf16.f32 "
                        "{%0,%1,%2,%3},{%4,%5,%6,%7},{%8,%9},{%0,%1,%2,%3};\n"
                        : "+f"(acc[mf][nf][0]), "+f"(acc[mf][nf][1]),
                          "+f"(acc[mf][nf][2]), "+f"(acc[mf][nf][3])
                        : "r"(af[mf][0]), "r"(af[mf][1]), "r"(af[mf][2]), "r"(af[mf][3]),
                          "r"(bfr[nf][0]), "r"(bfr[nf][1]));
                }
        }
        if (kc < 7) {
            #pragma unroll
            for (int i = 0; i < 4; i++) {
                int u = t + i * 256;
                int r = u >> 3, c2 = u & 7;
                ((uint2*)sA[buf ^ 1])[r * 10 + c2] = ra[i];
                ((uint2*)sB[buf ^ 1])[r * 10 + c2] = rb[i];
            }
            __syncthreads();
            buf ^= 1;
        }
    }

    // Epilogue: per-row (max, argmax) over this CTA's 128 columns, merge globally.
    #pragma unroll
    for (int mf = 0; mf < 2; mf++) {
        #pragma unroll
        for (int h = 0; h < 2; h++) {
            int gr = rowA + m0 + mf * 16 + qr + h * 8;
            float bv = -4.0f;
            int   bc = 0;
            #pragma unroll
            for (int nf = 0; nf < 8; nf++) {
                #pragma unroll
                for (int e = 0; e < 2; e++) {
                    int gc = rowB + n0 + nf * 8 + qc * 2 + e;
                    float v = acc[mf][nf][h * 2 + e];
                    if (gc == gr) v = -3.0f;   // exclude diagonal
                    if (v > bv) { bv = v; bc = gc; }
                }
            }
            // reduce across the 4 lanes (qc) sharing this row
            #pragma unroll
            for (int o = 1; o < 4; o <<= 1) {
                float ov = __shfl_xor_sync(0xffffffffu, bv, o);
                int   oc = __shfl_xor_sync(0xffffffffu, bc, o);
                if (ov > bv) { bv = ov; bc = oc; }
            }
            if (qc == 0) {
                unsigned int fu = __float_as_uint(bv);
                fu = (fu & 0x80000000u) ? ~fu : (fu | 0x80000000u);   // order-preserving
                unsigned long long key = ((unsigned long long)fu << 32) | (unsigned int)bc;
                atomicMax(&g_best[gr], key);
            }
        }
    }
}

// ---------------------------------------------------------------------------
// Kernel 3: exact fp32 refinement. One warp per row: dist = ||x_i - x_j + eps||,
// accumulate -log(dist + eps)/B into d_out.
// ---------------------------------------------------------------------------
__global__ void koleo_final(float* __restrict__ out, int B) {
    int warp = threadIdx.x >> 5, lane = threadIdx.x & 31;
    int row  = blockIdx.x * 8 + warp;
    int j    = (int)(g_best[row] & 0xffffffffull);
    const float* xi = g_xf + row * D;
    const float* xj = g_xf + j * D;
    float s = 0.f;
    #pragma unroll
    for (int k = lane; k < D; k += 32) {
        float d = xi[k] - xj[k] + 1e-8f;
        s += d * d;
    }
    #pragma unroll
    for (int o = 16; o; o >>= 1) s += __shfl_xor_sync(0xffffffffu, s, o);
    if (lane == 0) {
        float dist = sqrtf(s);
        atomicAdd(out, -logf(dist + 1e-8f) / (float)B);
    }
}

// ---------------------------------------------------------------------------
extern "C" void kernel_launch(void* const* d_in, const int* in_sizes, int n_in,
                              void* d_out, int out_size) {
    const float* student = (const float*)d_in[0];
    int B = in_sizes[0] / D / NCROPS;          // 8192
    float* out = (float*)d_out;

    koleo_normalize<<<B, D>>>(student, out);
    dim3 grid(B / 128, B / 128);
    koleo_gemm_argmax<<<grid, 256>>>(B);
    koleo_final<<<B / 8, 256>>>(out, B);
}

// round 11
// speedup vs baseline: 2.2073x; 2.2073x over previous
#include <cuda_runtime.h>
#include <cuda_bf16.h>
#include <stdint.h>
#include <math.h>

#define D      256
#define MAXB   8192
#define NCROPS 10
#define SROW   20          // smem row stride in 32-bit words (32 bf16 + 8 pad halves)
#define BUFW   (128*SROW)  // words per buffer per tile

// ---- scratch (device globals; allocation is forbidden) ---------------------
__device__ __align__(16) __nv_bfloat16 g_xh[MAXB * D];   // normalized x, bf16 (4 MB)
__device__ float                       g_norm[MAXB];     // max(||x_i||, eps)
__device__ unsigned long long          g_best[MAXB];     // (ordered_fp32<<32)|argmax idx

__device__ __forceinline__ unsigned int ordered_fp(float f) {
    unsigned int u = __float_as_uint(f);
    return (u & 0x80000000u) ? ~u : (u | 0x80000000u);
}
__device__ __forceinline__ uint32_t smem_u32(const void* p) {
    uint32_t a;
    asm("{ .reg .u64 t; cvta.to.shared.u64 t, %1; cvt.u32.u64 %0, t; }" : "=r"(a) : "l"(p));
    return a;
}

// ---------------------------------------------------------------------------
// Kernel 1: row norms + bf16 normalized copy; reset argmax keys and output.
// ---------------------------------------------------------------------------
__global__ void koleo_normalize(const float* __restrict__ s, float* __restrict__ out) {
    int row = blockIdx.x;
    int t   = threadIdx.x;                    // blockDim = 256 = D
    float v = s[row * D + t];
    float ss = v * v;
    #pragma unroll
    for (int o = 16; o; o >>= 1) ss += __shfl_xor_sync(0xffffffffu, ss, o);
    __shared__ float ws[8];
    if ((t & 31) == 0) ws[t >> 5] = ss;
    __syncthreads();
    if (t == 0) {
        float a = 0.f;
        #pragma unroll
        for (int i = 0; i < 8; i++) a += ws[i];
        float nrm = fmaxf(sqrtf(a), 1e-8f);
        ws[0] = nrm;
        g_norm[row] = nrm;
        g_best[row] = 0ull;                   // any real key beats 0
        if (row == 0) out[0] = 0.f;
    }
    __syncthreads();
    g_xh[row * D + t] = __float2bfloat16(v / ws[0]);
}

// ---------------------------------------------------------------------------
// Kernel 2: symmetric fused x@x^T argmax. Only upper-triangle 128x128 tiles
// (bn >= bm). mma.sync.m16n8k16 bf16 fed by ldmatrix.x4 from padded smem.
// Each tile contributes a row-argmax AND (for off-diagonal tiles) a
// column-argmax for the mirrored tile. Global merge via u64 atomicMax.
// ---------------------------------------------------------------------------
__global__ void __launch_bounds__(256) koleo_gemm_argmax(int Bn) {
    __shared__ uint32_t sA[2 * BUFW];
    __shared__ uint32_t sB[2 * BUFW];

    // triangular decode: i -> (bI >= bJ); tile rows = bJ*128, cols = bI*128
    int i = blockIdx.x;
    int r = (int)((sqrtf(8.0f * (float)i + 1.0f) - 1.0f) * 0.5f);
    while ((r + 1) * (r + 2) / 2 <= i) r++;
    while (r * (r + 1) / 2 > i) r--;
    const int bm = i - r * (r + 1) / 2;       // row-tile  (bm <= bn)
    const int bn = r;                         // col-tile
    const int rowA = bm * 128, rowB = bn * 128;

    const int t    = threadIdx.x;
    const int lane = t & 31, warp = t >> 5;
    const int wm = warp & 3, wn = warp >> 2;  // 4x2 warp grid
    const int m0 = wm * 32,  n0 = wn * 64;
    const int qr = lane >> 2, qc = lane & 3;

    const uint32_t sAb = smem_u32(sA), sBb = smem_u32(sB);
    // per-lane ldmatrix addresses (byte offsets within a buffer)
    const int aRow  = m0 + ((lane >> 3) & 1) * 8 + (lane & 7);
    const int aKoff = (lane >> 4) * 16;
    const int bRow  = n0 + (lane >> 4) * 8 + (lane & 7);
    const int bKoff = ((lane >> 3) & 1) * 16;

    float acc[2][8][4];
    #pragma unroll
    for (int mf = 0; mf < 2; mf++)
        #pragma unroll
        for (int nf = 0; nf < 8; nf++)
            #pragma unroll
            for (int e = 0; e < 4; e++) acc[mf][nf][e] = 0.f;

    const uint2* gp = (const uint2*)g_xh;     // 64 uint2 per 256-elem row
    uint2 ra[4], rb[4];
    #pragma unroll
    for (int v = 0; v < 4; v++) {
        int u = t + v * 256;
        int rr = u >> 3, c2 = u & 7;
        ra[v] = gp[(size_t)(rowA + rr) * 64 + c2];
        rb[v] = gp[(size_t)(rowB + rr) * 64 + c2];
    }
    #pragma unroll
    for (int v = 0; v < 4; v++) {
        int u = t + v * 256;
        int rr = u >> 3, c2 = u & 7;
        ((uint2*)sA)[rr * 10 + c2] = ra[v];
        ((uint2*)sB)[rr * 10 + c2] = rb[v];
    }
    __syncthreads();

    int buf = 0;
    for (int kc = 0; kc < 8; kc++) {          // K = 256 = 8 chunks of 32
        if (kc < 7) {
            #pragma unroll
            for (int v = 0; v < 4; v++) {
                int u = t + v * 256;
                int rr = u >> 3, c2 = u & 7;
                ra[v] = gp[(size_t)(rowA + rr) * 64 + (kc + 1) * 8 + c2];
                rb[v] = gp[(size_t)(rowB + rr) * 64 + (kc + 1) * 8 + c2];
            }
        }
        const uint32_t baseA = sAb + buf * (BUFW * 4);
        const uint32_t baseB = sBb + buf * (BUFW * 4);
        #pragma unroll
        for (int kk2 = 0; kk2 < 2; kk2++) {   // two k16 steps per chunk
            uint32_t af[2][4];
            #pragma unroll
            for (int mf = 0; mf < 2; mf++) {
                uint32_t ad = baseA + (uint32_t)((aRow + mf * 16) * 80 + kk2 * 32 + aKoff);
                asm volatile("ldmatrix.sync.aligned.m8n8.x4.shared.b16 {%0,%1,%2,%3}, [%4];"
                             : "=r"(af[mf][0]), "=r"(af[mf][1]),
                               "=r"(af[mf][2]), "=r"(af[mf][3]) : "r"(ad));
            }
            uint32_t bfr[8][2];
            #pragma unroll
            for (int nfp = 0; nfp < 4; nfp++) {
                uint32_t bd = baseB + (uint32_t)((bRow + nfp * 16) * 80 + kk2 * 32 + bKoff);
                asm volatile("ldmatrix.sync.aligned.m8n8.x4.shared.b16 {%0,%1,%2,%3}, [%4];"
                             : "=r"(bfr[nfp * 2][0]), "=r"(bfr[nfp * 2][1]),
                               "=r"(bfr[nfp * 2 + 1][0]), "=r"(bfr[nfp * 2 + 1][1]) : "r"(bd));
            }
            #pragma unroll
            for (int mf = 0; mf < 2; mf++)
                #pragma unroll
                for (int nf = 0; nf < 8; nf++) {
                    asm volatile(
                        "mma.sync.aligned.m16n8k16.row.col.f32.bf16.bf16.f32 "
                        "{%0,%1,%2,%3},{%4,%5,%6,%7},{%8,%9},{%0,%1,%2,%3};\n"
                        : "+f"(acc[mf][nf][0]), "+f"(acc[mf][nf][1]),
                          "+f"(acc[mf][nf][2]), "+f"(acc[mf][nf][3])
                        : "r"(af[mf][0]), "r"(af[mf][1]), "r"(af[mf][2]), "r"(af[mf][3]),
                          "r"(bfr[nf][0]), "r"(bfr[nf][1]));
                }
        }
        if (kc < 7) {
            #pragma unroll
            for (int v = 0; v < 4; v++) {
                int u = t + v * 256;
                int rr = u >> 3, c2 = u & 7;
                ((uint2*)sA)[(buf ^ 1) * (BUFW / 2) + rr * 10 + c2] = ra[v];
                ((uint2*)sB)[(buf ^ 1) * (BUFW / 2) + rr * 10 + c2] = rb[v];
            }
            __syncthreads();
            buf ^= 1;
        }
    }

    // ---- diagonal exclusion (tile bm == bn) ----
    if (bm == bn) {
        #pragma unroll
        for (int mf = 0; mf < 2; mf++)
            #pragma unroll
            for (int h = 0; h < 2; h++) {
                int lr = m0 + mf * 16 + qr + h * 8;    // local row
                #pragma unroll
                for (int nf = 0; nf < 8; nf++)
                    #pragma unroll
                    for (int e = 0; e < 2; e++) {
                        int lc = n0 + nf * 8 + qc * 2 + e;
                        if (lc == lr) acc[mf][nf][h * 2 + e] = -3.0f;
                    }
            }
    }

    // ---- row argmax: reduce over qc lanes, one atomic per (row, warp) ----
    #pragma unroll
    for (int mf = 0; mf < 2; mf++) {
        #pragma unroll
        for (int h = 0; h < 2; h++) {
            int gr = rowA + m0 + mf * 16 + qr + h * 8;
            float bv = -4.0f; int bc = rowB;
            #pragma unroll
            for (int nf = 0; nf < 8; nf++)
                #pragma unroll
                for (int e = 0; e < 2; e++) {
                    float v = acc[mf][nf][h * 2 + e];
                    if (v > bv) { bv = v; bc = rowB + n0 + nf * 8 + qc * 2 + e; }
                }
            #pragma unroll
            for (int o = 1; o < 4; o <<= 1) {
                float ov = __shfl_xor_sync(0xffffffffu, bv, o);
                int   oc = __shfl_xor_sync(0xffffffffu, bc, o);
                if (ov > bv) { bv = ov; bc = oc; }
            }
            if (qc == 0) {
                unsigned long long key =
                    ((unsigned long long)ordered_fp(bv) << 32) | (unsigned int)bc;
                atomicMax(&g_best[gr], key);
            }
        }
    }

    // ---- column argmax (serves the mirrored tile) for off-diagonal tiles ----
    if (bn > bm) {
        float cbv[16]; int cbr[16];
        #pragma unroll
        for (int nf = 0; nf < 8; nf++)
            #pragma unroll
            for (int e = 0; e < 2; e++) {
                int id = nf * 2 + e;
                float bv = -4.0f; int br = rowA;
                #pragma unroll
                for (int mf = 0; mf < 2; mf++)
                    #pragma unroll
                    for (int h = 0; h < 2; h++) {
                        float v = acc[mf][nf][h * 2 + e];
                        if (v > bv) { bv = v; br = rowA + m0 + mf * 16 + qr + h * 8; }
                    }
                cbv[id] = bv; cbr[id] = br;
            }
        #pragma unroll
        for (int o = 4; o < 32; o <<= 1) {     // reduce across qr lanes
            #pragma unroll
            for (int id = 0; id < 16; id++) {
                float ov = __shfl_xor_sync(0xffffffffu, cbv[id], o);
                int   orr = __shfl_xor_sync(0xffffffffu, cbr[id], o);
                if (ov > cbv[id]) { cbv[id] = ov; cbr[id] = orr; }
            }
        }
        if (qr == 0) {                         // lanes 0..3 hold column bests
            #pragma unroll
            for (int id = 0; id < 16; id++) {
                int gc = rowB + n0 + (id >> 1) * 8 + qc * 2 + (id & 1);
                unsigned long long key =
                    ((unsigned long long)ordered_fp(cbv[id]) << 32) | (unsigned int)cbr[id];
                atomicMax(&g_best[gc], key);
            }
        }
    }
}

// ---------------------------------------------------------------------------
// Kernel 3: exact fp32 distance from raw input + stored norms.
// ---------------------------------------------------------------------------
__global__ void koleo_final(const float* __restrict__ s, float* __restrict__ out, int Bn) {
    int warp = threadIdx.x >> 5, lane = threadIdx.x & 31;
    int row  = blockIdx.x * 8 + warp;
    int j    = (int)(g_best[row] & 0xffffffffull);
    float ni = g_norm[row], nj = g_norm[j];
    const float* xi = s + (size_t)row * D;
    const float* xj = s + (size_t)j * D;
    float acc = 0.f;
    #pragma unroll
    for (int k = lane; k < D; k += 32) {
        float d = xi[k] / ni - xj[k] / nj + 1e-8f;
        acc += d * d;
    }
    #pragma unroll
    for (int o = 16; o; o >>= 1) acc += __shfl_xor_sync(0xffffffffu, acc, o);
    if (lane == 0)
        atomicAdd(out, -logf(sqrtf(acc) + 1e-8f) / (float)Bn);
}

// ---------------------------------------------------------------------------
extern "C" void kernel_launch(void* const* d_in, const int* in_sizes, int n_in,
                              void* d_out, int out_size) {
    const float* student = (const float*)d_in[0];
    int B = in_sizes[0] / D / NCROPS;         // 8192
    float* out = (float*)d_out;

    koleo_normalize<<<B, D>>>(student, out);

    int T = B / 128;                          // 64 tiles per side
    int ntiles = T * (T + 1) / 2;             // 2080 upper-triangle tiles
    koleo_gemm_argmax<<<ntiles, 256>>>(B);

    koleo_final<<<B / 8, 256>>>(student, out, B);
}

// round 13
// speedup vs baseline: 3.0788x; 1.3948x over previous
#include <cuda_runtime.h>
#include <cuda_bf16.h>
#include <stdint.h>
#include <math.h>

#define D       256
#define MAXB    8192
#define NCROPS  10

// GEMM tiling: 128x128 CTA tile, BK=64 chunks, 3-stage cp.async pipeline.
#define RSTRIDE 144                   // smem row stride in bytes (128 data + 16 pad)
#define TILEB   (128 * RSTRIDE)       // one operand tile chunk: 18432 B
#define CHUNKB  (2 * TILEB)           // A + B chunk: 36864 B
#define NSTAGE  3
#define SMEM_SZ (NSTAGE * CHUNKB)     // 110592 B

// ---- scratch (device globals; allocation is forbidden) ---------------------
__device__ __align__(16) __nv_bfloat16 g_xh[MAXB * D];   // normalized x, bf16 (4 MB)
__device__ float                       g_norm[MAXB];     // max(||x_i||, eps)
__device__ unsigned long long          g_best[MAXB];     // (ordered_fp32<<32)|argmax idx

__device__ __forceinline__ unsigned int ordered_fp(float f) {
    unsigned int u = __float_as_uint(f);
    return (u & 0x80000000u) ? ~u : (u | 0x80000000u);
}
__device__ __forceinline__ uint32_t smem_u32(const void* p) {
    uint32_t a;
    asm("{ .reg .u64 t; cvta.to.shared.u64 t, %1; cvt.u32.u64 %0, t; }" : "=r"(a) : "l"(p));
    return a;
}
__device__ __forceinline__ void cp16(uint32_t dst, const void* src) {
    asm volatile("cp.async.cg.shared.global [%0], [%1], 16;" :: "r"(dst), "l"(src));
}

// ---------------------------------------------------------------------------
// Kernel 1: warp-per-row L2-normalize. 2x float4 loads, 1x uint4 bf16 store.
// ---------------------------------------------------------------------------
__global__ void koleo_normalize(const float4* __restrict__ s, float* __restrict__ out) {
    int warp = threadIdx.x >> 5, lane = threadIdx.x & 31;
    int row  = blockIdx.x * 8 + warp;
    float4 a = s[(size_t)row * 64 + lane * 2];
    float4 b = s[(size_t)row * 64 + lane * 2 + 1];
    float ss = a.x*a.x + a.y*a.y + a.z*a.z + a.w*a.w
             + b.x*b.x + b.y*b.y + b.z*b.z + b.w*b.w;
    #pragma unroll
    for (int o = 16; o; o >>= 1) ss += __shfl_xor_sync(0xffffffffu, ss, o);
    float nrm = fmaxf(sqrtf(ss), 1e-8f);
    float inv = 1.0f / nrm;
    if (lane == 0) {
        g_norm[row] = nrm;
        g_best[row] = 0ull;                           // any real key beats 0
        if (row == 0) out[0] = 0.f;
    }
    __nv_bfloat162 p0 = __floats2bfloat162_rn(a.x * inv, a.y * inv);
    __nv_bfloat162 p1 = __floats2bfloat162_rn(a.z * inv, a.w * inv);
    __nv_bfloat162 p2 = __floats2bfloat162_rn(b.x * inv, b.y * inv);
    __nv_bfloat162 p3 = __floats2bfloat162_rn(b.z * inv, b.w * inv);
    uint4 pk;
    pk.x = *(uint32_t*)&p0; pk.y = *(uint32_t*)&p1;
    pk.z = *(uint32_t*)&p2; pk.w = *(uint32_t*)&p3;
    *(uint4*)(g_xh + (size_t)row * D + lane * 8) = pk;
}

// ---------------------------------------------------------------------------
// Kernel 2: symmetric fused x@x^T argmax (upper-triangle 128x128 tiles only).
// cp.async 3-stage pipeline, ldmatrix.x4 -> mma.sync.m16n8k16 bf16.
// ---------------------------------------------------------------------------
__global__ void __launch_bounds__(256, 2) koleo_gemm_argmax(int Bn) {
    extern __shared__ __align__(16) char smem[];
    const uint32_t sb = smem_u32(smem);

    // triangular decode: blockIdx.x -> (bm <= bn)
    int i = blockIdx.x;
    int r = (int)((sqrtf(8.0f * (float)i + 1.0f) - 1.0f) * 0.5f);
    while ((r + 1) * (r + 2) / 2 <= i) r++;
    while (r * (r + 1) / 2 > i) r--;
    const int bm = i - r * (r + 1) / 2;
    const int bn = r;
    const int rowA = bm * 128, rowB = bn * 128;

    const int t    = threadIdx.x;
    const int lane = t & 31, warp = t >> 5;
    const int wm = warp & 3, wn = warp >> 2;          // 4x2 warp grid
    const int m0 = wm * 32,  n0 = wn * 64;
    const int qr = lane >> 2, qc = lane & 3;

    // per-lane ldmatrix row/koffset decomposition
    const int aRow  = m0 + ((lane >> 3) & 1) * 8 + (lane & 7);
    const int aKoff = (lane >> 4) * 16;
    const int bRow  = n0 + (lane >> 4) * 8 + (lane & 7);
    const int bKoff = ((lane >> 3) & 1) * 16;

    // cp.async addressing for this thread (4x 16B per operand tile per chunk)
    const int ldR = t >> 3, ldC = t & 7;              // row step 32 per i
    const char* gA = (const char*)(g_xh + (size_t)rowA * D) + ldR * 512 + ldC * 16;
    const char* gB = (const char*)(g_xh + (size_t)rowB * D) + ldR * 512 + ldC * 16;
    const uint32_t dOff = (uint32_t)(ldR * RSTRIDE + ldC * 16);

    float acc[2][8][4];
    #pragma unroll
    for (int mf = 0; mf < 2; mf++)
        #pragma unroll
        for (int nf = 0; nf < 8; nf++)
            #pragma unroll
            for (int e = 0; e < 4; e++) acc[mf][nf][e] = 0.f;

    // ---- prefetch chunks 0..2 ----
    #pragma unroll
    for (int kc = 0; kc < 3; kc++) {
        uint32_t base = sb + kc * CHUNKB;
        #pragma unroll
        for (int v = 0; v < 4; v++) {
            cp16(base + dOff + v * (32 * RSTRIDE),         gA + kc * 128 + v * (size_t)(32 * 512));
            cp16(base + dOff + v * (32 * RSTRIDE) + TILEB, gB + kc * 128 + v * (size_t)(32 * 512));
        }
        asm volatile("cp.async.commit_group;" ::: "memory");
    }

#define COMPUTE_CHUNK(BUF)                                                        \
    {                                                                             \
        const uint32_t baseA = sb + (BUF) * CHUNKB;                               \
        const uint32_t baseB = baseA + TILEB;                                     \
        _Pragma("unroll")                                                         \
        for (int kk2 = 0; kk2 < 4; kk2++) {                                       \
            uint32_t af[2][4];                                                    \
            _Pragma("unroll")                                                     \
            for (int mf = 0; mf < 2; mf++) {                                      \
                uint32_t ad = baseA + (uint32_t)((aRow + mf * 16) * RSTRIDE       \
                                                 + kk2 * 32 + aKoff);             \
                asm volatile("ldmatrix.sync.aligned.m8n8.x4.shared.b16 "          \
                             "{%0,%1,%2,%3}, [%4];"                               \
                             : "=r"(af[mf][0]), "=r"(af[mf][1]),                  \
                               "=r"(af[mf][2]), "=r"(af[mf][3]) : "r"(ad));       \
            }                                                                     \
            uint32_t bfr[8][2];                                                   \
            _Pragma("unroll")                                                     \
            for (int nfp = 0; nfp < 4; nfp++) {                                   \
                uint32_t bd = baseB + (uint32_t)((bRow + nfp * 16) * RSTRIDE      \
                                                 + kk2 * 32 + bKoff);             \
                asm volatile("ldmatrix.sync.aligned.m8n8.x4.shared.b16 "          \
                             "{%0,%1,%2,%3}, [%4];"                               \
                             : "=r"(bfr[nfp*2][0]), "=r"(bfr[nfp*2][1]),          \
                               "=r"(bfr[nfp*2+1][0]), "=r"(bfr[nfp*2+1][1])       \
                             : "r"(bd));                                          \
            }                                                                     \
            _Pragma("unroll")                                                     \
            for (int mf = 0; mf < 2; mf++)                                        \
                _Pragma("unroll")                                                 \
                for (int nf = 0; nf < 8; nf++) {                                  \
                    asm volatile(                                                 \
                        "mma.sync.aligned.m16n8k16.row.col.f32.bf16.bf16.f32 "    \
                        "{%0,%1,%2,%3},{%4,%5,%6,%7},{%8,%9},{%0,%1,%2,%3};\n"    \
                        : "+f"(acc[mf][nf][0]), "+f"(acc[mf][nf][1]),             \
                          "+f"(acc[mf][nf][2]), "+f"(acc[mf][nf][3])              \
                        : "r"(af[mf][0]), "r"(af[mf][1]),                         \
                          "r"(af[mf][2]), "r"(af[mf][3]),                         \
                          "r"(bfr[nf][0]), "r"(bfr[nf][1]));                      \
                }                                                                 \
        }                                                                         \
    }

    // chunk 0
    asm volatile("cp.async.wait_group 2;" ::: "memory");
    __syncthreads();
    COMPUTE_CHUNK(0);
    __syncthreads();                                  // all warps done reading buf0
    {                                                 // chunk 3 -> buf0
        uint32_t base = sb;
        #pragma unroll
        for (int v = 0; v < 4; v++) {
            cp16(base + dOff + v * (32 * RSTRIDE),         gA + 3 * 128 + v * (size_t)(32 * 512));
            cp16(base + dOff + v * (32 * RSTRIDE) + TILEB, gB + 3 * 128 + v * (size_t)(32 * 512));
        }
        asm volatile("cp.async.commit_group;" ::: "memory");
    }
    // chunk 1
    asm volatile("cp.async.wait_group 2;" ::: "memory");
    __syncthreads();
    COMPUTE_CHUNK(1);
    // chunk 2
    asm volatile("cp.async.wait_group 1;" ::: "memory");
    __syncthreads();
    COMPUTE_CHUNK(2);
    // chunk 3
    asm volatile("cp.async.wait_group 0;" ::: "memory");
    __syncthreads();
    COMPUTE_CHUNK(0);

    // ---- diagonal exclusion ----
    if (bm == bn) {
        #pragma unroll
        for (int mf = 0; mf < 2; mf++)
            #pragma unroll
            for (int h = 0; h < 2; h++) {
                int lr = m0 + mf * 16 + qr + h * 8;
                #pragma unroll
                for (int nf = 0; nf < 8; nf++)
                    #pragma unroll
                    for (int e = 0; e < 2; e++) {
                        int lc = n0 + nf * 8 + qc * 2 + e;
                        if (lc == lr) acc[mf][nf][h * 2 + e] = -3.0f;
                    }
            }
    }

    // ---- row argmax ----
    #pragma unroll
    for (int mf = 0; mf < 2; mf++) {
        #pragma unroll
        for (int h = 0; h < 2; h++) {
            int gr = rowA + m0 + mf * 16 + qr + h * 8;
            float bv = -4.0f; int bc = rowB;
            #pragma unroll
            for (int nf = 0; nf < 8; nf++)
                #pragma unroll
                for (int e = 0; e < 2; e++) {
                    float v = acc[mf][nf][h * 2 + e];
                    if (v > bv) { bv = v; bc = rowB + n0 + nf * 8 + qc * 2 + e; }
                }
            #pragma unroll
            for (int o = 1; o < 4; o <<= 1) {
                float ov = __shfl_xor_sync(0xffffffffu, bv, o);
                int   oc = __shfl_xor_sync(0xffffffffu, bc, o);
                if (ov > bv) { bv = ov; bc = oc; }
            }
            if (qc == 0) {
                unsigned long long key =
                    ((unsigned long long)ordered_fp(bv) << 32) | (unsigned int)bc;
                atomicMax(&g_best[gr], key);
            }
        }
    }

    // ---- column argmax (mirrored tile) for off-diagonal tiles ----
    if (bn > bm) {
        float cbv[16]; int cbr[16];
        #pragma unroll
        for (int nf = 0; nf < 8; nf++)
            #pragma unroll
            for (int e = 0; e < 2; e++) {
                int id = nf * 2 + e;
                float bv = -4.0f; int br = rowA;
                #pragma unroll
                for (int mf = 0; mf < 2; mf++)
                    #pragma unroll
                    for (int h = 0; h < 2; h++) {
                        float v = acc[mf][nf][h * 2 + e];
                        if (v > bv) { bv = v; br = rowA + m0 + mf * 16 + qr + h * 8; }
                    }
                cbv[id] = bv; cbr[id] = br;
            }
        #pragma unroll
        for (int o = 4; o < 32; o <<= 1) {
            #pragma unroll
            for (int id = 0; id < 16; id++) {
                float ov = __shfl_xor_sync(0xffffffffu, cbv[id], o);
                int   orr = __shfl_xor_sync(0xffffffffu, cbr[id], o);
                if (ov > cbv[id]) { cbv[id] = ov; cbr[id] = orr; }
            }
        }
        if (qr == 0) {
            #pragma unroll
            for (int id = 0; id < 16; id++) {
                int gc = rowB + n0 + (id >> 1) * 8 + qc * 2 + (id & 1);
                unsigned long long key =
                    ((unsigned long long)ordered_fp(cbv[id]) << 32) | (unsigned int)cbr[id];
                atomicMax(&g_best[gc], key);
            }
        }
    }
}

// ---------------------------------------------------------------------------
// Kernel 3: exact fp32 distance from raw input + stored norms.
// ---------------------------------------------------------------------------
__global__ void koleo_final(const float* __restrict__ s, float* __restrict__ out, int Bn) {
    int warp = threadIdx.x >> 5, lane = threadIdx.x & 31;
    int row  = blockIdx.x * 8 + warp;
    int j    = (int)(g_best[row] & 0xffffffffull);
    float ni = g_norm[row], nj = g_norm[j];
    const float* xi = s + (size_t)row * D;
    const float* xj = s + (size_t)j * D;
    float acc = 0.f;
    #pragma unroll
    for (int k = lane; k < D; k += 32) {
        float d = xi[k] / ni - xj[k] / nj + 1e-8f;
        acc += d * d;
    }
    #pragma unroll
    for (int o = 16; o; o >>= 1) acc += __shfl_xor_sync(0xffffffffu, acc, o);
    if (lane == 0)
        atomicAdd(out, -logf(sqrtf(acc) + 1e-8f) / (float)Bn);
}

// ---------------------------------------------------------------------------
extern "C" void kernel_launch(void* const* d_in, const int* in_sizes, int n_in,
                              void* d_out, int out_size) {
    const float* student = (const float*)d_in[0];
    int B = in_sizes[0] / D / NCROPS;                 // 8192
    float* out = (float*)d_out;

    koleo_normalize<<<B / 8, 256>>>((const float4*)student, out);

    static int cfg_done = 0;
    if (!cfg_done) {
        cudaFuncSetAttribute(koleo_gemm_argmax,
                             cudaFuncAttributeMaxDynamicSharedMemorySize, SMEM_SZ);
        cfg_done = 1;
    }
    int T = B / 128;                                  // 64 tiles per side
    int ntiles = T * (T + 1) / 2;                     // 2080
    koleo_gemm_argmax<<<ntiles, 256, SMEM_SZ>>>(B);

    koleo_final<<<B / 8, 256>>>(student, out, B);
}